// round 17
// baseline (speedup 1.0000x reference)
#include <cuda_runtime.h>
#include <cstdint>

#define BB   8
#define CC   256
#define CID  64
#define NN   4096
#define LOG2E 1.4426950408889634f

// Scratch (no allocations allowed)
__device__ float d_theta[BB * NN * CID];  // [b][n][k], pre-scaled by log2(e)
__device__ float d_phi  [BB * NN * CID];  // [b][n][k]
__device__ float d_gm   [BB * NN * CID];  // [b][n][k]
__device__ float d_y    [BB * NN * CID];  // [b][n][k]

__device__ __forceinline__ float ex2f(float x) {
    float y; asm("ex2.approx.f32 %0, %1;" : "=f"(y) : "f"(x)); return y;
}
__device__ __forceinline__ uint32_t smem_to_u32(const void* p) {
    uint32_t a;
    asm("{ .reg .u64 t; cvta.to.shared.u64 t, %1; cvt.u32.u64 %0, t; }"
        : "=r"(a) : "l"(p));
    return a;
}
__device__ __forceinline__ void cp_async16(uint32_t saddr, const void* gptr) {
    asm volatile("cp.async.ca.shared.global [%0], [%1], 16;"
                 :: "r"(saddr), "l"(__cvta_generic_to_global(gptr)));
}
#define CP_COMMIT() asm volatile("cp.async.commit_group;" ::: "memory")
#define CP_WAIT(n)  asm volatile("cp.async.wait_group %0;" :: "n"(n) : "memory")

// m16n8k8 tf32 mma (raw fp32 bits as tf32 operands; HW truncates mantissa)
__device__ __forceinline__ void mma8(float* d, const uint32_t* a,
                                     uint32_t b0, uint32_t b1) {
    asm volatile(
        "mma.sync.aligned.m16n8k8.row.col.f32.tf32.tf32.f32 "
        "{%0,%1,%2,%3}, {%4,%5,%6,%7}, {%8,%9}, {%0,%1,%2,%3};\n"
        : "+f"(d[0]), "+f"(d[1]), "+f"(d[2]), "+f"(d[3])
        : "r"(a[0]), "r"(a[1]), "r"(a[2]), "r"(a[3]), "r"(b0), "r"(b1));
}

#define FB(x) __float_as_uint(x)

// attn smem layout (floats): rows padded to 68 for conflict-free fragments.
// 64-col tiles: theta 128x68, phi/g 2x(64x68) each, L 128.
#define ROWP  68
#define TH_F  0
#define PHI_F 8704
#define G_F   17408
#define L_F   26112
#define OP_F  PHI_F
#define ATTN_SMEM_BYTES ((26112 + 128) * 4)   // 104,960 B -> 2 CTAs/SM

// ---------------------------------------------------------------------------
// Kernel 1: tf32 MMA 1x1-conv projections. grid (N/128, B, 3), 256 threads.
// out[n][ci] = sum_c x[c][n] * w[ci][c] (+bias)(*log2e for theta)
// A = x^T fragments read from skewed [k][n] tiles; B = w (k-major native).
// ---------------------------------------------------------------------------
#define PROJ_SMEM (24576 * 4)   // x: 2x[64][128] + w: 2x[64][64] floats

__global__ __launch_bounds__(256, 2)
void proj_tc(const float* __restrict__ x,
             const float* __restrict__ gw, const float* __restrict__ gb,
             const float* __restrict__ tw, const float* __restrict__ tb,
             const float* __restrict__ pw, const float* __restrict__ pb)
{
    extern __shared__ float psm[];
    const uint32_t su = smem_to_u32(psm);
    const int tid = threadIdx.x;
    const int lane = tid & 31, wid = tid >> 5;
    const int tq = lane & 3, gq = lane >> 2;
    const int rb = (wid & 3) * 32;   // n-rows
    const int cb = (wid >> 2) * 32;  // ci-cols
    const int n0 = blockIdx.x * 128;
    const int b  = blockIdx.y;
    const int pr = blockIdx.z;
    const float* w  = (pr == 0) ? tw : (pr == 1) ? pw : gw;
    const float* bi = (pr == 0) ? tb : (pr == 1) ? pb : gb;

    // chunk loader: x chunk [64 k][128 n] skewed, w chunk [64 ci][64 k] skewed
    auto load_chunk = [&](int kc, int buf) {
        const float* xsrc = x + ((size_t)(b * CC + kc)) * NN + n0;
        const uint32_t xd = su + (buf * 8192) * 4;
        #pragma unroll
        for (int i = 0; i < 8; i++) {
            const int idx = i * 256 + tid;
            const int row = idx >> 5, c4 = (idx & 31) << 2;
            cp_async16(xd + (row * 128 + ((c4 + 4 * row) & 127)) * 4,
                       xsrc + (size_t)row * NN + c4);
        }
        const float* wsrc = w + kc;
        const uint32_t wd = su + (16384 + buf * 4096) * 4;
        #pragma unroll
        for (int i = 0; i < 4; i++) {
            const int idx = i * 256 + tid;
            const int row = idx >> 4, c4 = (idx & 15) << 2;
            cp_async16(wd + (row * 64 + ((c4 + 4 * row) & 63)) * 4,
                       wsrc + row * CC + c4);
        }
    };

    load_chunk(0, 0); CP_COMMIT();
    load_chunk(64, 1); CP_COMMIT();
    CP_WAIT(1);
    __syncthreads();

    float f[2][4][4] = {};

    #pragma unroll 1
    for (int ch = 0; ch < 4; ch++) {
        const int buf = ch & 1;
        const float* xs = psm + buf * 8192;
        const float* ws = psm + 16384 + buf * 4096;
        #pragma unroll
        for (int ks = 0; ks < 8; ks++) {
            const int col = ks * 8 + tq;
            uint32_t A[2][4];
            #pragma unroll
            for (int m = 0; m < 2; m++) {
                const int n = rb + m * 16 + gq;
                A[m][0] = FB(xs[col * 128 + ((n + 4 * col) & 127)]);
                A[m][1] = FB(xs[col * 128 + ((n + 8 + 4 * col) & 127)]);
                A[m][2] = FB(xs[(col + 4) * 128 + ((n + 4 * (col + 4)) & 127)]);
                A[m][3] = FB(xs[(col + 4) * 128 + ((n + 8 + 4 * (col + 4)) & 127)]);
            }
            #pragma unroll
            for (int nf = 0; nf < 4; nf++) {
                const int ci = cb + nf * 8 + gq;
                const uint32_t b0 = FB(ws[ci * 64 + ((col + 4 * ci) & 63)]);
                const uint32_t b1 = FB(ws[ci * 64 + ((col + 4 + 4 * ci) & 63)]);
                mma8(f[0][nf], A[0], b0, b1);
                mma8(f[1][nf], A[1], b0, b1);
            }
        }
        __syncthreads();
        if (ch + 2 < 4) { load_chunk((ch + 2) * 64, buf); CP_COMMIT(); CP_WAIT(1); }
        else            { CP_WAIT(0); }
        __syncthreads();
    }

    float* outb = (pr == 0) ? d_theta : (pr == 1) ? d_phi : d_gm;
    const float sc = (pr == 0) ? LOG2E : 1.0f;
    #pragma unroll
    for (int nf = 0; nf < 4; nf++) {
        const int ci0 = cb + nf * 8 + 2 * tq;
        const float bv0 = __ldg(&bi[ci0]);
        const float bv1 = __ldg(&bi[ci0 + 1]);
        #pragma unroll
        for (int m = 0; m < 2; m++)
            #pragma unroll
            for (int h = 0; h < 2; h++) {
                const int row = rb + m * 16 + gq + h * 8;
                float2 v = make_float2((f[m][nf][h * 2 + 0] + bv0) * sc,
                                       (f[m][nf][h * 2 + 1] + bv1) * sc);
                *(float2*)&outb[((size_t)(b * NN + n0 + row)) * CID + ci0] = v;
            }
    }
}

// ---------------------------------------------------------------------------
// Kernel 2: tf32 mma.sync flash attention, 64-col tiles for 2 CTAs/SM.
// grid (N/128, B), 256 threads (8 warps: 4 row-groups x 2 col-halves of 64).
// ---------------------------------------------------------------------------
__device__ __forceinline__ void load_tile(int b, int jt, int buf,
                                          uint32_t smem_u, int tid)
{
    const int c0 = jt * 64;
    const float* ps = &d_phi[((size_t)(b * NN + c0)) * CID];
    const float* gs = &d_gm [((size_t)(b * NN + c0)) * CID];
    const uint32_t pd = smem_u + (PHI_F + buf * 4352) * 4;
    const uint32_t gd = smem_u + (G_F  + buf * 4352) * 4;
    #pragma unroll
    for (int i = 0; i < 4; i++) {
        const int idx = i * 256 + tid;
        const int row = idx >> 4, c4 = (idx & 15) << 2;
        cp_async16(pd + (row * ROWP + c4) * 4, ps + row * 64 + c4);
        cp_async16(gd + (row * ROWP + c4) * 4, gs + row * 64 + c4);
    }
}

__global__ __launch_bounds__(256, 2)
void attn_kernel()
{
    extern __shared__ float sm[];
    const uint32_t smem_u = smem_to_u32(sm);
    const int tid  = threadIdx.x;
    const int lane = tid & 31, wid = tid >> 5;
    const int warp_m = wid & 3, warp_n = wid >> 2;
    const int rb = warp_m * 32;     // warp row base within 128
    const int cb = warp_n * 32;     // warp col base within 64-col tile
    const int b  = blockIdx.y;
    const int r0 = blockIdx.x * 128;
    const int tq = lane & 3;        // threadID_in_group
    const int gq = lane >> 2;       // groupID

    if (tid < 128) sm[L_F + tid] = 0.0f;

    // prologue: theta + tile0, tile1
    {
        const float* tsrc = &d_theta[((size_t)(b * NN + r0)) * CID];
        #pragma unroll
        for (int i = 0; i < 8; i++) {
            const int idx = i * 256 + tid;
            const int row = idx >> 4, c4 = (idx & 15) << 2;
            cp_async16(smem_u + (TH_F + row * ROWP + c4) * 4, tsrc + row * 64 + c4);
        }
    }
    load_tile(b, 0, 0, smem_u, tid);
    CP_COMMIT();
    load_tile(b, 1, 1, smem_u, tid);
    CP_COMMIT();
    CP_WAIT(1);
    __syncthreads();

    float o[2][8][4];
    #pragma unroll
    for (int m = 0; m < 2; m++)
        #pragma unroll
        for (int nf = 0; nf < 8; nf++)
            #pragma unroll
            for (int r = 0; r < 4; r++) o[m][nf][r] = 0.0f;

    const uint32_t* th = (const uint32_t*)sm;  // TH_F == 0
    const int srcA = (lane & ~3) | (tq >> 1);
    const int srcB = srcA + 2;
    const bool odd = lane & 1;

    #pragma unroll 1
    for (int jt = 0; jt < 64; jt++) {
        const int buf = jt & 1;
        const uint32_t* phb = (const uint32_t*)&sm[PHI_F + buf * 4352];
        const uint32_t* gsb = (const uint32_t*)&sm[G_F  + buf * 4352];

        // ---- S = theta @ phi^T (warp covers 32 rows x 32 cols) ----
        float s[2][4][4];
        #pragma unroll
        for (int m = 0; m < 2; m++)
            #pragma unroll
            for (int nf = 0; nf < 4; nf++)
                #pragma unroll
                for (int r = 0; r < 4; r++) s[m][nf][r] = 0.0f;

        #pragma unroll
        for (int ks = 0; ks < 8; ks++) {
            const int col = ks * 8 + tq;
            uint32_t A[2][4];
            #pragma unroll
            for (int m = 0; m < 2; m++) {
                const int row = rb + m * 16 + gq;
                A[m][0] = th[row * ROWP + col];
                A[m][1] = th[(row + 8) * ROWP + col];
                A[m][2] = th[row * ROWP + col + 4];
                A[m][3] = th[(row + 8) * ROWP + col + 4];
            }
            #pragma unroll
            for (int nf = 0; nf < 4; nf++) {
                const int nr = cb + nf * 8 + gq;
                const uint32_t b0 = phb[nr * ROWP + col];
                const uint32_t b1 = phb[nr * ROWP + col + 4];
                mma8(s[0][nf], A[0], b0, b1);
                mma8(s[1][nf], A[1], b0, b1);
            }
        }

        // ---- exp (log2 domain) + row sums ----
        float ls[2][2] = {{0.f, 0.f}, {0.f, 0.f}};
        #pragma unroll
        for (int m = 0; m < 2; m++)
            #pragma unroll
            for (int nf = 0; nf < 4; nf++) {
                s[m][nf][0] = ex2f(s[m][nf][0]);
                s[m][nf][1] = ex2f(s[m][nf][1]);
                s[m][nf][2] = ex2f(s[m][nf][2]);
                s[m][nf][3] = ex2f(s[m][nf][3]);
                ls[m][0] += s[m][nf][0] + s[m][nf][1];
                ls[m][1] += s[m][nf][2] + s[m][nf][3];
            }
        #pragma unroll
        for (int m = 0; m < 2; m++)
            #pragma unroll
            for (int h = 0; h < 2; h++) {
                float v = ls[m][h];
                v += __shfl_xor_sync(0xffffffffu, v, 1);
                v += __shfl_xor_sync(0xffffffffu, v, 2);
                if (tq == 0)
                    atomicAdd(&sm[L_F + rb + m * 16 + h * 8 + gq], v);
            }

        // ---- O += P @ g (P fragments from registers via shfl permute) ----
        #pragma unroll
        for (int ks = 0; ks < 4; ks++) {
            uint32_t A[2][4];
            #pragma unroll
            for (int m = 0; m < 2; m++) {
                float u0 = __shfl_sync(0xffffffffu, s[m][ks][0], srcA);
                float u1 = __shfl_sync(0xffffffffu, s[m][ks][1], srcA);
                float v0 = __shfl_sync(0xffffffffu, s[m][ks][0], srcB);
                float v1 = __shfl_sync(0xffffffffu, s[m][ks][1], srcB);
                A[m][0] = __float_as_uint(odd ? u1 : u0);
                A[m][2] = __float_as_uint(odd ? v1 : v0);
                u0 = __shfl_sync(0xffffffffu, s[m][ks][2], srcA);
                u1 = __shfl_sync(0xffffffffu, s[m][ks][3], srcA);
                v0 = __shfl_sync(0xffffffffu, s[m][ks][2], srcB);
                v1 = __shfl_sync(0xffffffffu, s[m][ks][3], srcB);
                A[m][1] = __float_as_uint(odd ? u1 : u0);
                A[m][3] = __float_as_uint(odd ? v1 : v0);
            }
            const int krow = cb + ks * 8 + tq;
            #pragma unroll
            for (int nf = 0; nf < 8; nf++) {
                const uint32_t b0 = gsb[krow * ROWP + nf * 8 + gq];
                const uint32_t b1 = gsb[(krow + 4) * ROWP + nf * 8 + gq];
                mma8(o[0][nf], A[0], b0, b1);
                mma8(o[1][nf], A[1], b0, b1);
            }
        }

        __syncthreads();
        if (jt + 2 < 64) { load_tile(b, jt + 2, buf, smem_u, tid); CP_COMMIT(); }
        if (jt < 62) { CP_WAIT(1); } else { CP_WAIT(0); }
        __syncthreads();
    }

    // ---- epilogue: reduce col-half partials, normalize by l, store y ----
    if (warp_n == 1) {
        #pragma unroll
        for (int m = 0; m < 2; m++) {
            const int row = rb + m * 16 + gq;
            #pragma unroll
            for (int nf = 0; nf < 8; nf++) {
                *(float2*)&sm[OP_F + row * ROWP + nf * 8 + 2 * tq] =
                    make_float2(o[m][nf][0], o[m][nf][1]);
                *(float2*)&sm[OP_F + (row + 8) * ROWP + nf * 8 + 2 * tq] =
                    make_float2(o[m][nf][2], o[m][nf][3]);
            }
        }
    }
    __syncthreads();
    if (warp_n == 0) {
        #pragma unroll
        for (int m = 0; m < 2; m++) {
            const int row = rb + m * 16 + gq;
            const float inv0 = 1.0f / sm[L_F + row];
            const float inv1 = 1.0f / sm[L_F + row + 8];
            #pragma unroll
            for (int nf = 0; nf < 8; nf++) {
                const float2 q0 = *(const float2*)&sm[OP_F + row * ROWP + nf * 8 + 2 * tq];
                const float2 q1 = *(const float2*)&sm[OP_F + (row + 8) * ROWP + nf * 8 + 2 * tq];
                float2 y0 = make_float2((o[m][nf][0] + q0.x) * inv0,
                                        (o[m][nf][1] + q0.y) * inv0);
                float2 y1 = make_float2((o[m][nf][2] + q1.x) * inv1,
                                        (o[m][nf][3] + q1.y) * inv1);
                *(float2*)&d_y[((size_t)(b * NN + r0 + row)) * CID + nf * 8 + 2 * tq] = y0;
                *(float2*)&d_y[((size_t)(b * NN + r0 + row + 8)) * CID + nf * 8 + 2 * tq] = y1;
            }
        }
    }
}

// ---------------------------------------------------------------------------
// Kernel 3: tf32 MMA output proj + residual. grid (N/64, B), 256 threads.
// out[c][n] = sum_ci w_w[c][ci]*y[n][ci] + wb[c] + x[c][n]
// Both operands natively k-major: A = w_w [256][64], B = y [n][64].
// ---------------------------------------------------------------------------
#define OUT_SMEM ((16384 + 4096) * 4)  // w [256][64] + y [64][64] floats

__global__ __launch_bounds__(256, 2)
void out_tc(const float* __restrict__ x, const float* __restrict__ ww,
            const float* __restrict__ wb, float* __restrict__ out)
{
    extern __shared__ float osm[];
    const uint32_t su = smem_to_u32(osm);
    const int tid = threadIdx.x;
    const int lane = tid & 31, wid = tid >> 5;
    const int tq = lane & 3, gq = lane >> 2;
    const int rb = (wid & 3) * 64;   // c-rows (4 m-frags each)
    const int cb = (wid >> 2) * 32;  // n-cols (4 n-frags each)
    const int n0 = blockIdx.x * 64;
    const int b  = blockIdx.y;

    // load w [256][64] skewed
    #pragma unroll
    for (int i = 0; i < 16; i++) {
        const int idx = i * 256 + tid;
        const int row = idx >> 4, c4 = (idx & 15) << 2;
        cp_async16(su + (row * 64 + ((c4 + 4 * row) & 63)) * 4,
                   ww + row * CID + c4);
    }
    // load y tile [64][64] skewed
    #pragma unroll
    for (int i = 0; i < 4; i++) {
        const int idx = i * 256 + tid;
        const int row = idx >> 4, c4 = (idx & 15) << 2;
        cp_async16(su + (16384 + row * 64 + ((c4 + 4 * row) & 63)) * 4,
                   &d_y[((size_t)(b * NN + n0 + row)) * CID + c4]);
    }
    CP_COMMIT(); CP_WAIT(0);
    __syncthreads();

    const float* ws = osm;
    const float* ys = osm + 16384;
    float acc[4][4][4] = {};

    #pragma unroll
    for (int ks = 0; ks < 8; ks++) {
        const int col = ks * 8 + tq;
        uint32_t A[4][4];
        #pragma unroll
        for (int mf = 0; mf < 4; mf++) {
            const int c = rb + mf * 16 + gq;
            A[mf][0] = FB(ws[c * 64 + ((col + 4 * c) & 63)]);
            A[mf][1] = FB(ws[(c + 8) * 64 + ((col + 4 * (c + 8)) & 63)]);
            A[mf][2] = FB(ws[c * 64 + ((col + 4 + 4 * c) & 63)]);
            A[mf][3] = FB(ws[(c + 8) * 64 + ((col + 4 + 4 * (c + 8)) & 63)]);
        }
        #pragma unroll
        for (int nf = 0; nf < 4; nf++) {
            const int n = cb + nf * 8 + gq;
            const uint32_t b0 = FB(ys[n * 64 + ((col + 4 * n) & 63)]);
            const uint32_t b1 = FB(ys[n * 64 + ((col + 4 + 4 * n) & 63)]);
            #pragma unroll
            for (int mf = 0; mf < 4; mf++) mma8(acc[mf][nf], A[mf], b0, b1);
        }
    }

    #pragma unroll
    for (int mf = 0; mf < 4; mf++)
        #pragma unroll
        for (int h = 0; h < 2; h++) {
            const int c = rb + mf * 16 + gq + h * 8;
            const float wbc = __ldg(&wb[c]);
            #pragma unroll
            for (int nf = 0; nf < 4; nf++) {
                const int n = n0 + cb + nf * 8 + 2 * tq;
                const size_t base = ((size_t)(b * CC + c)) * NN + n;
                const float2 xv = *(const float2*)&x[base];
                float2 v = make_float2(acc[mf][nf][h * 2 + 0] + wbc + xv.x,
                                       acc[mf][nf][h * 2 + 1] + wbc + xv.y);
                *(float2*)&out[base] = v;
            }
        }
}

// ---------------------------------------------------------------------------
extern "C" void kernel_launch(void* const* d_in, const int* in_sizes, int n_in,
                              void* d_out, int out_size)
{
    const float* x   = (const float*)d_in[0];
    const float* gw  = (const float*)d_in[1];
    const float* gbb = (const float*)d_in[2];
    const float* tw  = (const float*)d_in[3];
    const float* tb  = (const float*)d_in[4];
    const float* pw  = (const float*)d_in[5];
    const float* pb  = (const float*)d_in[6];
    const float* ww  = (const float*)d_in[7];
    const float* wb  = (const float*)d_in[8];
    float* out = (float*)d_out;

    cudaFuncSetAttribute(proj_tc, cudaFuncAttributeMaxDynamicSharedMemorySize,
                         PROJ_SMEM);
    cudaFuncSetAttribute(attn_kernel, cudaFuncAttributeMaxDynamicSharedMemorySize,
                         ATTN_SMEM_BYTES);
    cudaFuncSetAttribute(out_tc, cudaFuncAttributeMaxDynamicSharedMemorySize,
                         OUT_SMEM);

    proj_tc<<<dim3(NN / 128, BB, 3), 256, PROJ_SMEM>>>(x, gw, gbb, tw, tb, pw, pb);
    attn_kernel<<<dim3(NN / 128, BB), 256, ATTN_SMEM_BYTES>>>();
    out_tc<<<dim3(NN / 64, BB), 256, OUT_SMEM>>>(x, ww, wb, out);
}